// round 15
// baseline (speedup 1.0000x reference)
#include <cuda_runtime.h>
#include <cuda_bf16.h>
#include <cstdint>

#define NPTS 1024
#define HDIM 32
#define TCH 8
#define NCH (NPTS / TCH)      // 128 chunks
#define ROWB 400u             // 100 floats per (seq,t) row
#define SEQB (8u * ROWB)      // 3200 B
#define BUFB (8u * SEQB)      // 25600 B (8 seqs per CTA)

typedef unsigned long long u64;
typedef unsigned int u32;

// ---------- scratch ----------
__device__ float g_a[NPTS * HDIM];
__device__ float g_c[(NPTS + 4) * HDIM];
__device__ float g_h1[NPTS * HDIM];

// ---------- helpers ----------
__device__ __forceinline__ u64 f2fma(u64 a, u64 b, u64 c) {
    u64 d;
    asm("fma.rn.f32x2 %0, %1, %2, %3;" : "=l"(d) : "l"(a), "l"(b), "l"(c));
    return d;
}
__device__ __forceinline__ u64 add2(u64 a, u64 b) {
    u64 d;
    asm("add.rn.f32x2 %0, %1, %2;" : "=l"(d) : "l"(a), "l"(b));
    return d;
}
__device__ __forceinline__ u64 pack2(float lo, float hi) {
    u64 r;
    asm("mov.b64 %0, {%1, %2};" : "=l"(r) : "f"(lo), "f"(hi));
    return r;
}
__device__ __forceinline__ float hsum2(u64 v) {
    float lo, hi;
    asm("mov.b64 {%0, %1}, %2;" : "=f"(lo), "=f"(hi) : "l"(v));
    return lo + hi;
}
__device__ __forceinline__ float tanh_hw(float x) {
    float y;
    asm("tanh.approx.f32 %0, %1;" : "=f"(y) : "f"(x));
    return y;
}
__device__ __forceinline__ float sig_hw(float x) {
    return fmaf(tanh_hw(0.5f * x), 0.5f, 0.5f);
}
__device__ __forceinline__ u32 smem_u32(const void* p) {
    u32 a;
    asm("{ .reg .u64 t; cvta.to.shared.u64 t, %1; cvt.u32.u64 %0, t; }"
        : "=r"(a) : "l"(p));
    return a;
}
__device__ __forceinline__ void sts32(u32 addr, float v) {
    asm volatile("st.shared.b32 [%0], %1;" :: "r"(addr), "f"(v) : "memory");
}
__device__ __forceinline__ void sts64(u32 addr, u64 v) {
    asm volatile("st.shared.b64 [%0], %1;" :: "r"(addr), "l"(v) : "memory");
}
__device__ __forceinline__ float lds32f(u32 addr) {
    float v;
    asm volatile("ld.shared.b32 %0, [%1];" : "=f"(v) : "r"(addr));
    return v;
}
__device__ __forceinline__ void lds_v2(u64& p0, u64& p1, u32 addr) {
    asm volatile("ld.shared.v2.u64 {%0, %1}, [%2];"
                 : "=l"(p0), "=l"(p1) : "r"(addr));
}
__device__ __forceinline__ u32 tf32_of(float x) {
    u32 r;
    asm("cvt.rna.tf32.f32 %0, %1;" : "=r"(r) : "f"(x));
    return r;
}
__device__ __forceinline__ void mma_tf32(float& c0, float& c1, float& c2, float& c3,
                                         u32 a0, u32 a1, u32 a2, u32 a3,
                                         u32 b0, u32 b1) {
    asm("mma.sync.aligned.m16n8k8.row.col.f32.tf32.tf32.f32 "
        "{%0,%1,%2,%3}, {%4,%5,%6,%7}, {%8,%9}, {%0,%1,%2,%3};"
        : "+f"(c0), "+f"(c1), "+f"(c2), "+f"(c3)
        : "r"(a0), "r"(a1), "r"(a2), "r"(a3), "r"(b0), "r"(b1));
}
__device__ __forceinline__ void bar_all() {
    asm volatile("bar.sync 0;" ::: "memory");
}

// ---------- precompute: a_i = (Wa-Wb)@x_i + b ; c_j = Wb@x_j ----------
template <int F>
__global__ void __launch_bounds__(256)
pre_kernel(const float* __restrict__ x, const float* __restrict__ w,
           const float* __restrict__ b, float* __restrict__ a,
           float* __restrict__ c) {
    int wq = threadIdx.x >> 5;
    int l = threadIdx.x & 31;
    int i = blockIdx.x * 8 + wq;
    if (i >= NPTS) return;
    float av = b[l];
    float cv = 0.0f;
    const float* wr = w + l * (2 * F);
    const float* xr = x + i * F;
#pragma unroll
    for (int f = 0; f < F; ++f) {
        float xv = xr[f];
        float wa = wr[f];
        float wb = wr[F + f];
        av = fmaf(wa - wb, xv, av);
        cv = fmaf(wb, xv, cv);
    }
    a[i * HDIM + l] = av;
    c[i * HDIM + l] = cv;
}

// ---------- fused GRU: MMA producers + 2-seq consumers ----------
// 256 threads: warps 0-3 consumers (2 seqs each), warps 4-7 producers (2 seqs).
// Consumer w handles seqs {2w, 2w+1}; producer pw=wid-4 produces the same pair.
// wid%4 mapping puts exactly 1 consumer + 1 producer on each SMSP.
// Two independent recurrence chains per consumer warp -> static ILP hides
// the LDS/MUFU chain latency without relying on the warp arbiter.
template <int FUSE_CLF>
__global__ void __launch_bounds__(256, 1)
gru_fused_kernel(const float* __restrict__ a, const float* __restrict__ c,
                 const float* __restrict__ wih, const float* __restrict__ whh,
                 const float* __restrict__ bih, const float* __restrict__ bhh,
                 const float* __restrict__ clf_w, const float* __restrict__ clf_b,
                 float* __restrict__ out) {
    __shared__ __align__(16) float s_xg[2][8][TCH][100];  // ring: 51200 B
    __shared__ __align__(16) float s_h[8][2][HDIM];

    const int wid = threadIdx.x >> 5;
    const int l = threadIdx.x & 31;
    const u32 xgb = smem_u32(&s_xg[0][0][0][0]);

    if (wid < 4) {
        // ===================== consumer (2 sequences) =====================
        const int w = wid;
        const int sA = 2 * w, sB = sA + 1;
        const int iA = blockIdx.x * 8 + sA;
        const int iB = iA + 1;

        u64 Whr[16], Whz[16], Whn[16];
        {
            const u64* pr = (const u64*)(whh + (0 * HDIM + l) * HDIM);
            const u64* pz = (const u64*)(whh + (1 * HDIM + l) * HDIM);
            const u64* pn = (const u64*)(whh + (2 * HDIM + l) * HDIM);
#pragma unroll
            for (int q = 0; q < 16; ++q) {
                Whr[q] = pr[q];
                Whz[q] = pz[q];
                Whn[q] = pn[q];
            }
        }
        const u64 init_r = pack2(bih[l] + bhh[l], 0.0f);
        const u64 init_z = pack2(bih[HDIM + l] + bhh[HDIM + l], 0.0f);
        const u64 init_n = pack2(bhh[2 * HDIM + l], 0.0f);  // b_hn
        const float b_xn = bih[2 * HDIM + l];

        const u32 hbA = smem_u32(&s_h[sA][0][0]);
        const u32 hbB = smem_u32(&s_h[sB][0][0]);
        const u32 xA = xgb + (u32)sA * SEQB;
        const u32 xB = xgb + (u32)sB * SEQB;

        float hA = 0.0f, hB = 0.0f;

        for (int k = 0; k <= NCH; ++k) {
            if (k > 0) {
                const u32 boff = (u32)((k - 1) & 1) * BUFB;
                const u32 xcA = xA + boff;
                const u32 xcB = xB + boff;
#pragma unroll
                for (int t = 0; t < TCH; ++t) {
                    const u32 ro = (u32)t * ROWB + (u32)l * 4u;
                    const float xrA = lds32f(xcA + ro);
                    const float xzA = lds32f(xcA + ro + 128u);
                    const float xnA = lds32f(xcA + ro + 256u);
                    const float xrB = lds32f(xcB + ro);
                    const float xzB = lds32f(xcB + ro + 128u);
                    const float xnB = lds32f(xcB + ro + 256u);

                    const u32 po = (u32)(t & 1) * 128u;
                    sts32(hbA + po + l * 4u, hA);
                    sts32(hbB + po + l * 4u, hB);
                    __syncwarp();

                    u64 rA0 = init_r, rA1 = 0ULL, zA0 = init_z, zA1 = 0ULL;
                    u64 nA0 = init_n, nA1 = 0ULL;
                    u64 rB0 = init_r, rB1 = 0ULL, zB0 = init_z, zB1 = 0ULL;
                    u64 nB0 = init_n, nB1 = 0ULL;
#pragma unroll
                    for (int q = 0; q < 8; ++q) {
                        u64 pa0, pa1, pb0, pb1;
                        lds_v2(pa0, pa1, hbA + po + q * 16u);
                        lds_v2(pb0, pb1, hbB + po + q * 16u);
                        rA0 = f2fma(Whr[2 * q], pa0, rA0);
                        rA1 = f2fma(Whr[2 * q + 1], pa1, rA1);
                        rB0 = f2fma(Whr[2 * q], pb0, rB0);
                        rB1 = f2fma(Whr[2 * q + 1], pb1, rB1);
                        zA0 = f2fma(Whz[2 * q], pa0, zA0);
                        zA1 = f2fma(Whz[2 * q + 1], pa1, zA1);
                        zB0 = f2fma(Whz[2 * q], pb0, zB0);
                        zB1 = f2fma(Whz[2 * q + 1], pb1, zB1);
                        nA0 = f2fma(Whn[2 * q], pa0, nA0);
                        nA1 = f2fma(Whn[2 * q + 1], pa1, nA1);
                        nB0 = f2fma(Whn[2 * q], pb0, nB0);
                        nB1 = f2fma(Whn[2 * q + 1], pb1, nB1);
                    }
                    const float rA = sig_hw(xrA + hsum2(add2(rA0, rA1)));
                    const float rB = sig_hw(xrB + hsum2(add2(rB0, rB1)));
                    const float zA = sig_hw(xzA + hsum2(add2(zA0, zA1)));
                    const float zB = sig_hw(xzB + hsum2(add2(zB0, zB1)));
                    const float nA = tanh_hw(fmaf(rA, hsum2(add2(nA0, nA1)), xnA + b_xn));
                    const float nB = tanh_hw(fmaf(rB, hsum2(add2(nB0, nB1)), xnB + b_xn));
                    hA = fmaf(zA, hA - nA, nA);
                    hB = fmaf(zB, hB - nB, nB);
                }
            }
            bar_all();
        }

        if (FUSE_CLF) {
            sts32(hbA + l * 4u, hA);
            sts32(hbB + l * 4u, hB);
            __syncwarp();
            if (l < 3) {
                float accA = clf_b[l];
                float accB = clf_b[l];
                const float* cw = clf_w + l * HDIM;
#pragma unroll
                for (int hh = 0; hh < HDIM; ++hh) {
                    accA = fmaf(cw[hh], s_h[sA][0][hh], accA);
                    accB = fmaf(cw[hh], s_h[sB][0][hh], accB);
                }
                out[iA * 3 + l] = accA;
                out[iB * 3 + l] = accB;
            }
        } else {
            out[iA * HDIM + l] = hA;
            out[iB * HDIM + l] = hB;
        }
    } else {
        // ===================== producer (MMA, 2 sequences) =====================
        const int pw = wid - 4;            // 0..3
        const int s0 = pw * 2, s1 = s0 + 1;
        const int g = l >> 2, tig = l & 3;

        u32 Bf[12][4][2];
#pragma unroll
        for (int nt = 0; nt < 12; ++nt) {
            const float* wr = wih + (nt * 8 + g) * HDIM;
#pragma unroll
            for (int kc = 0; kc < 4; ++kc) {
                Bf[nt][kc][0] = tf32_of(wr[kc * 8 + tig]);
                Bf[nt][kc][1] = tf32_of(wr[kc * 8 + tig + 4]);
            }
        }
        const int i0 = blockIdx.x * 8 + s0;
        const int i1 = i0 + 1;
        float av00[4], av01[4], av10[4], av11[4];
#pragma unroll
        for (int kc = 0; kc < 4; ++kc) {
            av00[kc] = a[i0 * HDIM + kc * 8 + tig];
            av01[kc] = a[i0 * HDIM + kc * 8 + tig + 4];
            av10[kc] = a[i1 * HDIM + kc * 8 + tig];
            av11[kc] = a[i1 * HDIM + kc * 8 + tig + 4];
        }

        for (int k = 0; k <= NCH; ++k) {
            if (k < NCH) {
                const int j0 = k * TCH;
                const float* cr = c + (j0 + g) * HDIM;
                const u32 base0 = xgb + (u32)(k & 1) * BUFB + (u32)s0 * SEQB + (u32)g * ROWB;
                const u32 base1 = xgb + (u32)(k & 1) * BUFB + (u32)s1 * SEQB + (u32)g * ROWB;
#pragma unroll
                for (int half = 0; half < 2; ++half) {
                    float acc[6][4];
#pragma unroll
                    for (int nn = 0; nn < 6; ++nn) {
                        acc[nn][0] = 0.0f; acc[nn][1] = 0.0f;
                        acc[nn][2] = 0.0f; acc[nn][3] = 0.0f;
                    }
#pragma unroll
                    for (int kc = 0; kc < 4; ++kc) {
                        const float cv0 = cr[kc * 8 + tig];
                        const float cv1 = cr[kc * 8 + tig + 4];
                        const float u0 = fmaxf(av00[kc] + cv0, 0.0f);  // row g    (s0)
                        const float u1 = fmaxf(av10[kc] + cv0, 0.0f);  // row g+8  (s1)
                        const float u2 = fmaxf(av01[kc] + cv1, 0.0f);
                        const float u3 = fmaxf(av11[kc] + cv1, 0.0f);
                        const u32 h0 = tf32_of(u0), h1 = tf32_of(u1);
                        const u32 h2 = tf32_of(u2), h3 = tf32_of(u3);
                        const u32 lo0 = tf32_of(u0 - __uint_as_float(h0));
                        const u32 lo1 = tf32_of(u1 - __uint_as_float(h1));
                        const u32 lo2 = tf32_of(u2 - __uint_as_float(h2));
                        const u32 lo3 = tf32_of(u3 - __uint_as_float(h3));
#pragma unroll
                        for (int nn = 0; nn < 6; ++nn) {
                            const int nt = half * 6 + nn;
                            mma_tf32(acc[nn][0], acc[nn][1], acc[nn][2], acc[nn][3],
                                     h0, h1, h2, h3, Bf[nt][kc][0], Bf[nt][kc][1]);
                            mma_tf32(acc[nn][0], acc[nn][1], acc[nn][2], acc[nn][3],
                                     lo0, lo1, lo2, lo3, Bf[nt][kc][0], Bf[nt][kc][1]);
                        }
                    }
#pragma unroll
                    for (int nn = 0; nn < 6; ++nn) {
                        const int nt = half * 6 + nn;
                        const u32 cb = (u32)(nt * 8 + 2 * tig) * 4u;
                        sts64(base0 + cb, pack2(acc[nn][0], acc[nn][1]));
                        sts64(base1 + cb, pack2(acc[nn][2], acc[nn][3]));
                    }
                }
            }
            bar_all();
        }
    }
}

extern "C" void kernel_launch(void* const* d_in, const int* in_sizes, int n_in,
                              void* d_out, int out_size) {
    const float* x        = (const float*)d_in[0];
    const float* proj1_w  = (const float*)d_in[1];
    const float* proj1_b  = (const float*)d_in[2];
    const float* gru1_wih = (const float*)d_in[3];
    const float* gru1_whh = (const float*)d_in[4];
    const float* gru1_bih = (const float*)d_in[5];
    const float* gru1_bhh = (const float*)d_in[6];
    const float* proj2_w  = (const float*)d_in[7];
    const float* proj2_b  = (const float*)d_in[8];
    const float* gru2_wih = (const float*)d_in[9];
    const float* gru2_whh = (const float*)d_in[10];
    const float* gru2_bih = (const float*)d_in[11];
    const float* gru2_bhh = (const float*)d_in[12];
    const float* clf_w    = (const float*)d_in[13];
    const float* clf_b    = (const float*)d_in[14];
    float* out = (float*)d_out;

    float *pa, *pc, *ph1;
    cudaGetSymbolAddress((void**)&pa, g_a);
    cudaGetSymbolAddress((void**)&pc, g_c);
    cudaGetSymbolAddress((void**)&ph1, g_h1);

    // Stage 1
    pre_kernel<16><<<128, 256>>>(x, proj1_w, proj1_b, pa, pc);
    gru_fused_kernel<0><<<128, 256>>>(pa, pc, gru1_wih, gru1_whh, gru1_bih,
                                      gru1_bhh, nullptr, nullptr, ph1);
    // Stage 2
    pre_kernel<32><<<128, 256>>>(ph1, proj2_w, proj2_b, pa, pc);
    gru_fused_kernel<1><<<128, 256>>>(pa, pc, gru2_wih, gru2_whh, gru2_bih,
                                      gru2_bhh, clf_w, clf_b, out);
}